// round 11
// baseline (speedup 1.0000x reference)
#include <cuda_runtime.h>
#include <cuda_bf16.h>
#include <math.h>

// ---------------- problem constants ----------------
#define BATCH 64
#define HDIM  2048
#define SEQ   2048
#define NH    32
#define NKV   4
#define GQA   8          // NH/NKV
#define HD    128
#define NEXP  32
#define IDIM  768
#define TOPK  4
#define QKV_N 5120       // (NH+2*NKV)*HD
#define EPS   1e-6f
#define SCHUNK 256
#define NCHUNK (SEQ / SCHUNK)   // 8
#define PD 4                    // GEMM pipeline depth (STATIC unroll)

// ---------------- scratch (device globals) ----------------
// Scratch passed as kernel ARGUMENTS must be resolved via cudaGetSymbolAddress
// (host &g_x is the ATS host shadow — rounds 1-5 bug). In-kernel refs ok.
__device__ float g_hn   [BATCH * HDIM];
__device__ float g_qkv  [BATCH * QKV_N];
__device__ float g_attn [BATCH * NH * HD];
__device__ float g_hs2  [BATCH * HDIM];
__device__ float g_h2   [BATCH * HDIM];
__device__ float g_act  [NEXP * BATCH * IDIM];
__device__ float g_ypair[BATCH * TOPK * HDIM];
__device__ float g_part [8 * BATCH * QKV_N / 2];
__device__ int   g_cnt  [NEXP];
__device__ int   g_tok  [NEXP * BATCH];
__device__ int   g_slot [NEXP * BATCH];
__device__ float g_wt   [NEXP * BATCH];
// split-S attention partials
__device__ float g_pm [BATCH * NKV * NCHUNK * GQA];
__device__ float g_pl [BATCH * NKV * NCHUNK * GQA];
__device__ float g_po [BATCH * NKV * NCHUNK * GQA * HD];

// ---------------- packed fp32x2 FMA (sm_100+; IEEE fp32 per lane) ----------------
__device__ __forceinline__ float2 ffma2(float2 a, float2 b, float2 c) {
    unsigned long long ua = *reinterpret_cast<unsigned long long*>(&a);
    unsigned long long ub = *reinterpret_cast<unsigned long long*>(&b);
    unsigned long long uc = *reinterpret_cast<unsigned long long*>(&c);
    unsigned long long ud;
    asm("fma.rn.f32x2 %0, %1, %2, %3;" : "=l"(ud) : "l"(ua), "l"(ub), "l"(uc));
    return *reinterpret_cast<float2*>(&ud);
}

// ---------------- reset routing counters ----------------
__global__ void reset_k() {
    if (threadIdx.x < NEXP) g_cnt[threadIdx.x] = 0;
}

// ---------------- RMSNorm (block per token) ----------------
__global__ __launch_bounds__(256) void rmsnorm_k(
    const float* __restrict__ x, const float* __restrict__ w, float* __restrict__ y)
{
    int b = blockIdx.x, tid = threadIdx.x;
    const float* xb = x + b * HDIM;
    float s = 0.f;
    for (int i = tid; i < HDIM; i += 256) { float v = xb[i]; s += v * v; }
    for (int o = 16; o; o >>= 1) s += __shfl_xor_sync(0xffffffffu, s, o);
    __shared__ float red[8];
    __shared__ float inv;
    if ((tid & 31) == 0) red[tid >> 5] = s;
    __syncthreads();
    if (tid == 0) {
        float t = 0.f;
        #pragma unroll
        for (int i = 0; i < 8; i++) t += red[i];
        inv = rsqrtf(t * (1.f / HDIM) + EPS);
    }
    __syncthreads();
    float iv = inv;
    for (int i = tid; i < HDIM; i += 256) y[b * HDIM + i] = xb[i] * iv * w[i];
}

// ---------------- GEMM partial: static 4-deep pipeline + FFMA2 ----------------
// BM=64 BN=64 BK=16; A stored DUPLICATED in smem ({a,a} pairs) so ffma2 lane
// pairs come straight from LDS.128 with no broadcast MOVs.
__global__ __launch_bounds__(256) void gemm_part_k(
    const float* __restrict__ A, const float* __restrict__ W,
    float* __restrict__ part, int N, int K, int ksplit)
{
    __shared__ float As[PD][16][136];   // duplicated: [k][2*m+{0,1}]
    __shared__ float Ws[PD][16][68];
    int nb = blockIdx.x * 64;
    int ks = blockIdx.y;
    int klen = K / ksplit;
    int kbeg = ks * klen;
    int tiles = klen / 16;
    int tid = threadIdx.x;

    int lm = tid >> 2;            // 0..63
    int lk = (tid & 3) * 4;       // 0,4,8,12
    const float* Ag = A + (long)lm * K + kbeg + lk;
    const float* Wg = W + (long)(nb + lm) * K + kbeg + lk;

    int tx = tid & 15, ty = tid >> 4;
    float2 acc2[4][2] = {};

    float4 rA[PD], rW[PD];
    #pragma unroll
    for (int s = 0; s < PD; s++) {
        rA[s] = *(const float4*)(Ag + s * 16);
        rW[s] = *(const float4*)(Wg + s * 16);
    }

    for (int t = 0; t < tiles; t += PD) {
        #pragma unroll
        for (int p = 0; p < PD; p++) {           // p compile-time after unroll
            *(float2*)&As[p][lk+0][2*lm] = make_float2(rA[p].x, rA[p].x);
            *(float2*)&As[p][lk+1][2*lm] = make_float2(rA[p].y, rA[p].y);
            *(float2*)&As[p][lk+2][2*lm] = make_float2(rA[p].z, rA[p].z);
            *(float2*)&As[p][lk+3][2*lm] = make_float2(rA[p].w, rA[p].w);
            Ws[p][lk+0][lm] = rW[p].x; Ws[p][lk+1][lm] = rW[p].y;
            Ws[p][lk+2][lm] = rW[p].z; Ws[p][lk+3][lm] = rW[p].w;
            if (t + p + PD < tiles) {
                rA[p] = *(const float4*)(Ag + (t + p + PD) * 16);
                rW[p] = *(const float4*)(Wg + (t + p + PD) * 16);
            }
            __syncthreads();
            #pragma unroll
            for (int kk = 0; kk < 16; kk++) {
                float4 w  = *(const float4*)&Ws[p][kk][tx * 4];
                float4 d0 = *(const float4*)&As[p][kk][ty * 8];
                float4 d1 = *(const float4*)&As[p][kk][ty * 8 + 4];
                float2 wlo = make_float2(w.x, w.y);
                float2 whi = make_float2(w.z, w.w);
                acc2[0][0] = ffma2(make_float2(d0.x, d0.y), wlo, acc2[0][0]);
                acc2[0][1] = ffma2(make_float2(d0.x, d0.y), whi, acc2[0][1]);
                acc2[1][0] = ffma2(make_float2(d0.z, d0.w), wlo, acc2[1][0]);
                acc2[1][1] = ffma2(make_float2(d0.z, d0.w), whi, acc2[1][1]);
                acc2[2][0] = ffma2(make_float2(d1.x, d1.y), wlo, acc2[2][0]);
                acc2[2][1] = ffma2(make_float2(d1.x, d1.y), whi, acc2[2][1]);
                acc2[3][0] = ffma2(make_float2(d1.z, d1.w), wlo, acc2[3][0]);
                acc2[3][1] = ffma2(make_float2(d1.z, d1.w), whi, acc2[3][1]);
            }
            __syncthreads();
        }
    }

    #pragma unroll
    for (int i = 0; i < 4; i++) {
        float4 v = make_float4(acc2[i][0].x, acc2[i][0].y, acc2[i][1].x, acc2[i][1].y);
        *(float4*)&part[((long)(ks * 64 + ty * 4 + i)) * N + nb + tx * 4] = v;
    }
}

// ---------------- GEMM reduce: C = sum_ks part + bias (+res) ----------------
__global__ __launch_bounds__(256) void gemm_reduce_k(
    const float* __restrict__ part, const float* __restrict__ bias,
    const float* __restrict__ res, float* __restrict__ C, int N, int ksplit)
{
    int idx = (blockIdx.x * 256 + threadIdx.x) * 4;
    int m = idx / N, n = idx % N;
    float4 s = bias ? *(const float4*)&bias[n] : make_float4(0.f, 0.f, 0.f, 0.f);
    for (int ks = 0; ks < ksplit; ks++) {
        float4 p = *(const float4*)&part[((long)(ks * 64 + m)) * N + n];
        s.x += p.x; s.y += p.y; s.z += p.z; s.w += p.w;
    }
    if (res) {
        float4 r = *(const float4*)&res[idx];
        s.x += r.x; s.y += r.y; s.z += r.z; s.w += r.w;
    }
    *(float4*)&C[idx] = s;
}

// ---------------- split-S GQA flash-decode: partial per (b, kv, chunk) ----------------
__global__ __launch_bounds__(256) void attn_part_k(
    const float* __restrict__ kc, const float* __restrict__ vc,
    const int* __restrict__ seq_lens)
{
    int c  = blockIdx.x;
    int kv = blockIdx.y;
    int b  = blockIdx.z;
    int tid = threadIdx.x, warp = tid >> 5, lane = tid & 31;
    int sl = seq_lens[b];
    if (sl < 0) sl = 0;
    if (sl > SEQ - 1) sl = SEQ - 1;
    int L  = sl + 1;
    int s0 = c * SCHUNK;
    if (s0 >= L) return;
    int s1 = s0 + SCHUNK; if (s1 > L) s1 = L;
    const float scale = 0.08838834764831845f;

    const float* qbase = g_qkv + b * QKV_N + kv * GQA * HD;
    const float* knew  = g_qkv + b * QKV_N + NH * HD + kv * HD;
    const float* vnew  = g_qkv + b * QKV_N + (NH + NKV) * HD + kv * HD;

    float4 q[GQA];
    #pragma unroll
    for (int h = 0; h < GQA; h++) q[h] = *(const float4*)(qbase + h * HD + lane * 4);

    float m[GQA], l[GQA];
    float4 o[GQA];
    #pragma unroll
    for (int h = 0; h < GQA; h++) {
        m[h] = -INFINITY; l[h] = 0.f; o[h] = make_float4(0.f, 0.f, 0.f, 0.f);
    }

    int s = s0 + warp;
    if (s < s1) {
        const float* kp = (s == sl) ? knew : (kc + ((size_t)(b * SEQ + s) * NKV + kv) * HD);
        const float* vp = (s == sl) ? vnew : (vc + ((size_t)(b * SEQ + s) * NKV + kv) * HD);
        float4 kk = *(const float4*)(kp + lane * 4);
        float4 vv = *(const float4*)(vp + lane * 4);
        for (;;) {
            int sn = s + 8;
            float4 knx, vnx;
            if (sn < s1) {
                const float* kp2 = (sn == sl) ? knew : (kc + ((size_t)(b * SEQ + sn) * NKV + kv) * HD);
                const float* vp2 = (sn == sl) ? vnew : (vc + ((size_t)(b * SEQ + sn) * NKV + kv) * HD);
                knx = *(const float4*)(kp2 + lane * 4);
                vnx = *(const float4*)(vp2 + lane * 4);
            }
            #pragma unroll
            for (int h = 0; h < GQA; h++) {
                float d = q[h].x * kk.x + q[h].y * kk.y + q[h].z * kk.z + q[h].w * kk.w;
                d += __shfl_xor_sync(0xffffffffu, d, 16);
                d += __shfl_xor_sync(0xffffffffu, d, 8);
                d += __shfl_xor_sync(0xffffffffu, d, 4);
                d += __shfl_xor_sync(0xffffffffu, d, 2);
                d += __shfl_xor_sync(0xffffffffu, d, 1);
                float sc = d * scale;
                float nm = fmaxf(m[h], sc);
                float corr = __expf(m[h] - nm);
                float p = __expf(sc - nm);
                l[h] = l[h] * corr + p;
                o[h].x = o[h].x * corr + p * vv.x;
                o[h].y = o[h].y * corr + p * vv.y;
                o[h].z = o[h].z * corr + p * vv.z;
                o[h].w = o[h].w * corr + p * vv.w;
                m[h] = nm;
            }
            if (sn >= s1) break;
            s = sn; kk = knx; vv = vnx;
        }
    }

    __shared__ float sm[8][GQA], sll[8][GQA];
    __shared__ float so[8][GQA][HD];
    #pragma unroll
    for (int h = 0; h < GQA; h++) {
        if (lane == 0) { sm[warp][h] = m[h]; sll[warp][h] = l[h]; }
        *(float4*)&so[warp][h][lane * 4] = o[h];
    }
    __syncthreads();

    int pbase = ((b * NKV + kv) * NCHUNK + c) * GQA;
    for (int idx = tid; idx < GQA * HD; idx += 256) {
        int h = idx >> 7, d = idx & (HD - 1);
        float M = -INFINITY;
        #pragma unroll
        for (int w = 0; w < 8; w++) M = fmaxf(M, sm[w][h]);
        float acc = 0.f, Ls = 0.f;
        #pragma unroll
        for (int w = 0; w < 8; w++) {
            float cw = __expf(sm[w][h] - M);
            acc += cw * so[w][h][d];
            Ls  += cw * sll[w][h];
        }
        g_po[(pbase + h) * HD + d] = acc;
        if (d == 0) { g_pm[pbase + h] = M; g_pl[pbase + h] = Ls; }
    }
}

// ---------------- combine split-S partials ----------------
__global__ __launch_bounds__(256) void attn_comb_k(
    const int* __restrict__ seq_lens, float* __restrict__ out)
{
    int b  = blockIdx.x >> 2;
    int kv = blockIdx.x & 3;
    int tid = threadIdx.x;
    int sl = seq_lens[b];
    if (sl < 0) sl = 0;
    if (sl > SEQ - 1) sl = SEQ - 1;
    int nch = sl / SCHUNK + 1;
    int base = (b * NKV + kv) * NCHUNK;

    for (int idx = tid; idx < GQA * HD; idx += 256) {
        int h = idx >> 7, d = idx & (HD - 1);
        float M = -INFINITY;
        for (int c = 0; c < nch; c++) M = fmaxf(M, g_pm[(base + c) * GQA + h]);
        float acc = 0.f, Ls = 0.f;
        for (int c = 0; c < nch; c++) {
            float w = __expf(g_pm[(base + c) * GQA + h] - M);
            acc += w * g_po[((base + c) * GQA + h) * HD + d];
            Ls  += w * g_pl[(base + c) * GQA + h];
        }
        out[b * NH * HD + (kv * GQA + h) * HD + d] = acc / Ls;
    }
}

// ---------------- gate: logits, top4, routing tables ----------------
__global__ __launch_bounds__(256) void gate_k(const float* __restrict__ gw)
{
    int b = blockIdx.x, tid = threadIdx.x, warp = tid >> 5, lane = tid & 31;
    __shared__ float lg[NEXP];
    const float* h = g_h2 + b * HDIM;
    for (int e = warp; e < NEXP; e += 8) {
        const float* g = gw + e * HDIM;
        float s = 0.f;
        for (int i = lane; i < HDIM; i += 32) s += h[i] * g[i];
        for (int o = 16; o; o >>= 1) s += __shfl_xor_sync(0xffffffffu, s, o);
        if (lane == 0) lg[e] = s;
    }
    __syncthreads();
    if (tid == 0) {
        float val[TOPK]; int idx[TOPK];
        unsigned used = 0;
        for (int j = 0; j < TOPK; j++) {
            float best = -1e30f; int bi = 0;
            for (int e = 0; e < NEXP; e++)
                if (!((used >> e) & 1u) && lg[e] > best) { best = lg[e]; bi = e; }
            used |= 1u << bi; val[j] = best; idx[j] = bi;
        }
        float s = 0.f, wj[TOPK];
        for (int j = 0; j < TOPK; j++) { wj[j] = expf(val[j] - val[0]); s += wj[j]; }
        float is = 1.f / s;
        for (int j = 0; j < TOPK; j++) {
            int e = idx[j];
            int pos = atomicAdd(&g_cnt[e], 1);
            g_tok [e * BATCH + pos] = b;
            g_slot[e * BATCH + pos] = j;
            g_wt  [e * BATCH + pos] = wj[j] * is;
        }
    }
}

// ---------------- MoE w1: static 4-deep pipeline + FFMA2, BM=16 BN=64 BK=16 ------
// A stored DUPLICATED ({a,a}); tiles = HDIM/16 = 128 (mult of PD)
__global__ __launch_bounds__(256) void moe_w1_k(const float* __restrict__ w1)
{
    int e = blockIdx.y;
    int cnt = g_cnt[e];
    int m0 = blockIdx.z * 16;
    if (m0 >= cnt) return;
    int ib = blockIdx.x * 64;

    __shared__ float As[PD][16][34];    // duplicated: [k][2*m+{0,1}]
    __shared__ float Gs[PD][16][68];
    __shared__ float Us[PD][16][68];
    __shared__ int toks[16];

    int tid = threadIdx.x;
    if (tid < 16) toks[tid] = (m0 + tid < cnt) ? g_tok[e * BATCH + m0 + tid]
                                               : g_tok[e * BATCH];
    __syncthreads();

    int am = tid >> 4, ak = tid & 15;
    int ln = tid >> 2, lk = (tid & 3) * 4;
    const float* Agp = g_h2 + (long)toks[am] * HDIM + ak;
    const float* Ggp = w1 + ((long)e * 2 * IDIM + ib + ln) * HDIM + lk;
    const float* Ugp = Ggp + (long)IDIM * HDIM;

    int tx = tid & 15, ty = tid >> 4;
    float2 ag2[2] = {}, au2[2] = {};

    float  rAa[PD];
    float4 rG[PD], rU[PD];
    const int tiles = HDIM / 16;   // 128
    #pragma unroll
    for (int s = 0; s < PD; s++) {
        rAa[s] = *(Agp + s * 16);
        rG[s]  = *(const float4*)(Ggp + s * 16);
        rU[s]  = *(const float4*)(Ugp + s * 16);
    }

    for (int t = 0; t < tiles; t += PD) {
        #pragma unroll
        for (int p = 0; p < PD; p++) {
            *(float2*)&As[p][ak][2*am] = make_float2(rAa[p], rAa[p]);
            Gs[p][lk+0][ln] = rG[p].x; Gs[p][lk+1][ln] = rG[p].y;
            Gs[p][lk+2][ln] = rG[p].z; Gs[p][lk+3][ln] = rG[p].w;
            Us[p][lk+0][ln] = rU[p].x; Us[p][lk+1][ln] = rU[p].y;
            Us[p][lk+2][ln] = rU[p].z; Us[p][lk+3][ln] = rU[p].w;
            if (t + p + PD < tiles) {
                rAa[p] = *(Agp + (t + p + PD) * 16);
                rG[p]  = *(const float4*)(Ggp + (t + p + PD) * 16);
                rU[p]  = *(const float4*)(Ugp + (t + p + PD) * 16);
            }
            __syncthreads();
            #pragma unroll
            for (int kk = 0; kk < 16; kk++) {
                float2 ap = *(const float2*)&As[p][kk][ty * 2];   // {a,a}
                float4 g4 = *(const float4*)&Gs[p][kk][tx * 4];
                float4 u4 = *(const float4*)&Us[p][kk][tx * 4];
                ag2[0] = ffma2(ap, make_float2(g4.x, g4.y), ag2[0]);
                ag2[1] = ffma2(ap, make_float2(g4.z, g4.w), ag2[1]);
                au2[0] = ffma2(ap, make_float2(u4.x, u4.y), au2[0]);
                au2[1] = ffma2(ap, make_float2(u4.z, u4.w), au2[1]);
            }
            __syncthreads();
        }
    }

    int m = m0 + ty;
    if (m < cnt) {
        float gv[4] = {ag2[0].x, ag2[0].y, ag2[1].x, ag2[1].y};
        float uv[4] = {au2[0].x, au2[0].y, au2[1].x, au2[1].y};
        float4 v;
        float* vp = (float*)&v;
        #pragma unroll
        for (int j = 0; j < 4; j++) {
            float g = gv[j];
            vp[j] = g / (1.f + expf(-g)) * uv[j];
        }
        *(float4*)&g_act[(long)(e * BATCH + m) * IDIM + ib + tx * 4] = v;
    }
}

// ---------------- MoE w2: static 4-deep pipeline + FFMA2, BM=16 BN=64 BK=16 ------
// tiles = IDIM/16 = 48 (mult of PD)
__global__ __launch_bounds__(256) void moe_w2_k(const float* __restrict__ w2)
{
    int e = blockIdx.y;
    int cnt = g_cnt[e];
    int m0 = blockIdx.z * 16;
    if (m0 >= cnt) return;
    int hb = blockIdx.x * 64;

    __shared__ float As[PD][16][34];    // duplicated
    __shared__ float Ws[PD][16][68];

    int tid = threadIdx.x;
    int am = tid >> 4, ak = tid & 15;
    int ln = tid >> 2, lk = (tid & 3) * 4;
    const float* Agp = g_act + (long)(e * BATCH + m0 + am) * IDIM + ak;
    const float* Wgp = w2 + ((long)e * HDIM + hb + ln) * IDIM + lk;

    int tx = tid & 15, ty = tid >> 4;
    float2 acc2[2] = {};

    float  rAa[PD];
    float4 rW[PD];
    const int tiles = IDIM / 16;   // 48
    #pragma unroll
    for (int s = 0; s < PD; s++) {
        rAa[s] = *(Agp + s * 16);
        rW[s]  = *(const float4*)(Wgp + s * 16);
    }

    for (int t = 0; t < tiles; t += PD) {
        #pragma unroll
        for (int p = 0; p < PD; p++) {
            *(float2*)&As[p][ak][2*am] = make_float2(rAa[p], rAa[p]);
            Ws[p][lk+0][ln] = rW[p].x; Ws[p][lk+1][ln] = rW[p].y;
            Ws[p][lk+2][ln] = rW[p].z; Ws[p][lk+3][ln] = rW[p].w;
            if (t + p + PD < tiles) {
                rAa[p] = *(Agp + (t + p + PD) * 16);
                rW[p]  = *(const float4*)(Wgp + (t + p + PD) * 16);
            }
            __syncthreads();
            #pragma unroll
            for (int kk = 0; kk < 16; kk++) {
                float2 ap = *(const float2*)&As[p][kk][ty * 2];
                float4 w4 = *(const float4*)&Ws[p][kk][tx * 4];
                acc2[0] = ffma2(ap, make_float2(w4.x, w4.y), acc2[0]);
                acc2[1] = ffma2(ap, make_float2(w4.z, w4.w), acc2[1]);
            }
            __syncthreads();
        }
    }

    int m = m0 + ty;
    if (m < cnt) {
        int tok = g_tok [e * BATCH + m];
        int j   = g_slot[e * BATCH + m];
        float w = g_wt  [e * BATCH + m];
        float4 v = make_float4(w * acc2[0].x, w * acc2[0].y, w * acc2[1].x, w * acc2[1].y);
        *(float4*)&g_ypair[(long)(tok * TOPK + j) * HDIM + hb + tx * 4] = v;
    }
}

// ---------------- finalize: out = hs2 + sum_j ypair ----------------
__global__ __launch_bounds__(256) void finalize_k(float* __restrict__ out)
{
    int idx = blockIdx.x * 256 + threadIdx.x;
    int tok = idx >> 11, hh = idx & (HDIM - 1);
    float s = g_hs2[idx];
    #pragma unroll
    for (int j = 0; j < TOPK; j++) s += g_ypair[(tok * TOPK + j) * HDIM + hh];
    out[idx] = s;
}

// ---------------- launch ----------------
extern "C" void kernel_launch(void* const* d_in, const int* in_sizes, int n_in,
                              void* d_out, int out_size)
{
    static float *p_hn = 0, *p_qkv = 0, *p_attn = 0, *p_hs2 = 0, *p_h2 = 0, *p_part = 0;
    if (!p_hn) {
        cudaGetSymbolAddress((void**)&p_hn,   g_hn);
        cudaGetSymbolAddress((void**)&p_qkv,  g_qkv);
        cudaGetSymbolAddress((void**)&p_attn, g_attn);
        cudaGetSymbolAddress((void**)&p_hs2,  g_hs2);
        cudaGetSymbolAddress((void**)&p_h2,   g_h2);
        cudaGetSymbolAddress((void**)&p_part, g_part);
    }

    const float *hidden = 0, *k_cache = 0, *v_cache = 0, *w_qkv = 0, *b_qkv = 0;
    const float *w_o = 0, *ln1_w = 0, *ln2_w = 0, *gate_w = 0, *w1 = 0, *w2 = 0;
    const int *positions = 0, *seqlens = 0;

    for (int i = 0; i < n_in; i++) {
        long sz = (long)in_sizes[i];
        const void* p = d_in[i];
        if      (sz == (long)BATCH * HDIM)            hidden = (const float*)p;
        else if (sz == (long)BATCH) {
            if (!positions) positions = (const int*)p; else seqlens = (const int*)p;
        }
        else if (sz == (long)BATCH * SEQ * NKV * HD) {
            if (!k_cache) k_cache = (const float*)p; else v_cache = (const float*)p;
        }
        else if (sz == (long)QKV_N * HDIM)            w_qkv  = (const float*)p;
        else if (sz == (long)QKV_N)                   b_qkv  = (const float*)p;
        else if (sz == (long)HDIM * NH * HD)          w_o    = (const float*)p;
        else if (sz == (long)HDIM) {
            if (!ln1_w) ln1_w = (const float*)p; else ln2_w = (const float*)p;
        }
        else if (sz == (long)NEXP * HDIM)             gate_w = (const float*)p;
        else if (sz == (long)NEXP * 2 * IDIM * HDIM)  w1     = (const float*)p;
        else if (sz == (long)NEXP * HDIM * IDIM)      w2     = (const float*)p;
    }
    if (!seqlens && positions) seqlens = positions;
    if (!v_cache) v_cache = k_cache;
    if (!ln2_w)   ln2_w   = ln1_w;

    float* out = (float*)d_out;

    reset_k<<<1, 32>>>();
    rmsnorm_k<<<BATCH, 256>>>(hidden, ln1_w, p_hn);
    gemm_part_k<<<dim3(QKV_N / 64, 4), 256>>>(p_hn, w_qkv, p_part, QKV_N, HDIM, 4);
    gemm_reduce_k<<<(64 * QKV_N) / 1024, 256>>>(p_part, b_qkv, nullptr, p_qkv, QKV_N, 4);
    attn_part_k<<<dim3(NCHUNK, NKV, BATCH), 256>>>(k_cache, v_cache, seqlens);
    attn_comb_k<<<BATCH * NKV, 256>>>(seqlens, p_attn);
    gemm_part_k<<<dim3(HDIM / 64, 8), 256>>>(p_attn, w_o, p_part, HDIM, NH * HD, 8);
    gemm_reduce_k<<<(64 * HDIM) / 1024, 256>>>(p_part, nullptr, hidden, p_hs2, HDIM, 8);
    rmsnorm_k<<<BATCH, 256>>>(p_hs2, ln2_w, p_h2);
    gate_k<<<BATCH, 256>>>(gate_w);
    moe_w1_k<<<dim3(IDIM / 64, NEXP, 4), 256>>>(w1);
    moe_w2_k<<<dim3(HDIM / 64, NEXP, 4), 256>>>(w2);
    finalize_k<<<(BATCH * HDIM) / 256, 256>>>(out);
}

// round 12
// speedup vs baseline: 1.0933x; 1.0933x over previous
#include <cuda_runtime.h>
#include <cuda_bf16.h>
#include <math.h>

// ---------------- problem constants ----------------
#define BATCH 64
#define HDIM  2048
#define SEQ   2048
#define NH    32
#define NKV   4
#define GQA   8          // NH/NKV
#define HD    128
#define NEXP  32
#define IDIM  768
#define TOPK  4
#define QKV_N 5120       // (NH+2*NKV)*HD
#define EPS   1e-6f
#define SCHUNK 256
#define NCHUNK (SEQ / SCHUNK)   // 8
#define PD 4                    // GEMM pipeline depth (STATIC unroll)

// ---------------- scratch (device globals) ----------------
// Scratch passed as kernel ARGUMENTS must be resolved via cudaGetSymbolAddress
// (host &g_x is the ATS host shadow — rounds 1-5 bug). In-kernel refs ok.
__device__ float g_hn   [BATCH * HDIM];
__device__ float g_qkv  [BATCH * QKV_N];
__device__ float g_attn [BATCH * NH * HD];
__device__ float g_hs2  [BATCH * HDIM];
__device__ float g_h2   [BATCH * HDIM];
__device__ float g_act  [NEXP * BATCH * IDIM];
__device__ float g_ypair[BATCH * TOPK * HDIM];
__device__ float g_part [4 * BATCH * QKV_N];   // K-split partials (qkv 4x, wo 8x fits)
__device__ int   g_cnt  [NEXP];
__device__ int   g_tok  [NEXP * BATCH];
__device__ int   g_slot [NEXP * BATCH];
__device__ float g_wt   [NEXP * BATCH];
// split-S attention partials
__device__ float g_pm [BATCH * NKV * NCHUNK * GQA];
__device__ float g_pl [BATCH * NKV * NCHUNK * GQA];
__device__ float g_po [BATCH * NKV * NCHUNK * GQA * HD];

// ---------------- reset routing counters ----------------
__global__ void reset_k() {
    if (threadIdx.x < NEXP) g_cnt[threadIdx.x] = 0;
}

// ---------------- RMSNorm (block per token) ----------------
__global__ __launch_bounds__(256) void rmsnorm_k(
    const float* __restrict__ x, const float* __restrict__ w, float* __restrict__ y)
{
    int b = blockIdx.x, tid = threadIdx.x;
    const float* xb = x + b * HDIM;
    float s = 0.f;
    for (int i = tid; i < HDIM; i += 256) { float v = xb[i]; s += v * v; }
    for (int o = 16; o; o >>= 1) s += __shfl_xor_sync(0xffffffffu, s, o);
    __shared__ float red[8];
    __shared__ float inv;
    if ((tid & 31) == 0) red[tid >> 5] = s;
    __syncthreads();
    if (tid == 0) {
        float t = 0.f;
        #pragma unroll
        for (int i = 0; i < 8; i++) t += red[i];
        inv = rsqrtf(t * (1.f / HDIM) + EPS);
    }
    __syncthreads();
    float iv = inv;
    for (int i = tid; i < HDIM; i += 256) y[b * HDIM + i] = xb[i] * iv * w[i];
}

// ---------------- GEMM partial: BM=64 BN=128 BK=16, 4m x 8n, PD4 static ---------
// tiles (= K/ksplit/16) MUST be a multiple of PD (32, 32 here).
__global__ __launch_bounds__(256) void gemm_part_k(
    const float* __restrict__ A, const float* __restrict__ W,
    float* __restrict__ part, int N, int K, int ksplit)
{
    __shared__ float As[PD][16][68];    // [k][m]
    __shared__ float Ws[PD][16][132];   // [k][n] (two 64-halves)
    int nb = blockIdx.x * 128;
    int ks = blockIdx.y;
    int klen = K / ksplit;
    int kbeg = ks * klen;
    int tiles = klen / 16;
    int tid = threadIdx.x;

    // A loader: 64 rows x 16k, one float4/thread
    int lm = tid >> 2;            // 0..63
    int lk = (tid & 3) * 4;       // 0,4,8,12
    const float* Ag = A + (long)lm * K + kbeg + lk;
    // W loader: 128 rows x 16k, two float4/thread
    int lw = tid & 127;           // row 0..127
    int kq = (tid >> 7) * 8;      // 0 or 8
    const float* Wg = W + (long)(nb + lw) * K + kbeg + kq;

    int tx = tid & 15, ty = tid >> 4;
    float acc[4][8] = {};

    float4 rA[PD], rW0[PD], rW1[PD];
    #pragma unroll
    for (int s = 0; s < PD; s++) {
        rA[s]  = *(const float4*)(Ag + s * 16);
        rW0[s] = *(const float4*)(Wg + s * 16);
        rW1[s] = *(const float4*)(Wg + s * 16 + 4);
    }

    for (int t = 0; t < tiles; t += PD) {
        #pragma unroll
        for (int p = 0; p < PD; p++) {           // p compile-time after unroll
            As[p][lk+0][lm] = rA[p].x; As[p][lk+1][lm] = rA[p].y;
            As[p][lk+2][lm] = rA[p].z; As[p][lk+3][lm] = rA[p].w;
            Ws[p][kq+0][lw] = rW0[p].x; Ws[p][kq+1][lw] = rW0[p].y;
            Ws[p][kq+2][lw] = rW0[p].z; Ws[p][kq+3][lw] = rW0[p].w;
            Ws[p][kq+4][lw] = rW1[p].x; Ws[p][kq+5][lw] = rW1[p].y;
            Ws[p][kq+6][lw] = rW1[p].z; Ws[p][kq+7][lw] = rW1[p].w;
            if (t + p + PD < tiles) {
                rA[p]  = *(const float4*)(Ag + (t + p + PD) * 16);
                rW0[p] = *(const float4*)(Wg + (t + p + PD) * 16);
                rW1[p] = *(const float4*)(Wg + (t + p + PD) * 16 + 4);
            }
            __syncthreads();
            #pragma unroll
            for (int kk = 0; kk < 16; kk++) {
                float4 a  = *(const float4*)&As[p][kk][ty * 4];
                float4 w0 = *(const float4*)&Ws[p][kk][tx * 4];
                float4 w1 = *(const float4*)&Ws[p][kk][64 + tx * 4];
                float av[4] = {a.x, a.y, a.z, a.w};
                float wv[8] = {w0.x, w0.y, w0.z, w0.w, w1.x, w1.y, w1.z, w1.w};
                #pragma unroll
                for (int i = 0; i < 4; i++)
                    #pragma unroll
                    for (int j = 0; j < 8; j++)
                        acc[i][j] = fmaf(av[i], wv[j], acc[i][j]);
            }
            __syncthreads();
        }
    }

    #pragma unroll
    for (int i = 0; i < 4; i++) {
        long row = (long)(ks * 64 + ty * 4 + i) * N;
        *(float4*)&part[row + nb + tx * 4] =
            make_float4(acc[i][0], acc[i][1], acc[i][2], acc[i][3]);
        *(float4*)&part[row + nb + 64 + tx * 4] =
            make_float4(acc[i][4], acc[i][5], acc[i][6], acc[i][7]);
    }
}

// ---------------- GEMM reduce: C = sum_ks part + bias (+res) ----------------
__global__ __launch_bounds__(256) void gemm_reduce_k(
    const float* __restrict__ part, const float* __restrict__ bias,
    const float* __restrict__ res, float* __restrict__ C, int N, int ksplit)
{
    int idx = (blockIdx.x * 256 + threadIdx.x) * 4;
    int m = idx / N, n = idx % N;
    float4 s = bias ? *(const float4*)&bias[n] : make_float4(0.f, 0.f, 0.f, 0.f);
    for (int ks = 0; ks < ksplit; ks++) {
        float4 p = *(const float4*)&part[((long)(ks * 64 + m)) * N + n];
        s.x += p.x; s.y += p.y; s.z += p.z; s.w += p.w;
    }
    if (res) {
        float4 r = *(const float4*)&res[idx];
        s.x += r.x; s.y += r.y; s.z += r.z; s.w += r.w;
    }
    *(float4*)&C[idx] = s;
}

// ---------------- split-S GQA flash-decode: partial per (b, kv, chunk) ----------------
__global__ __launch_bounds__(256) void attn_part_k(
    const float* __restrict__ kc, const float* __restrict__ vc,
    const int* __restrict__ seq_lens)
{
    int c  = blockIdx.x;
    int kv = blockIdx.y;
    int b  = blockIdx.z;
    int tid = threadIdx.x, warp = tid >> 5, lane = tid & 31;
    int sl = seq_lens[b];
    if (sl < 0) sl = 0;
    if (sl > SEQ - 1) sl = SEQ - 1;
    int L  = sl + 1;
    int s0 = c * SCHUNK;
    if (s0 >= L) return;
    int s1 = s0 + SCHUNK; if (s1 > L) s1 = L;
    const float scale = 0.08838834764831845f;

    const float* qbase = g_qkv + b * QKV_N + kv * GQA * HD;
    const float* knew  = g_qkv + b * QKV_N + NH * HD + kv * HD;
    const float* vnew  = g_qkv + b * QKV_N + (NH + NKV) * HD + kv * HD;

    float4 q[GQA];
    #pragma unroll
    for (int h = 0; h < GQA; h++) q[h] = *(const float4*)(qbase + h * HD + lane * 4);

    float m[GQA], l[GQA];
    float4 o[GQA];
    #pragma unroll
    for (int h = 0; h < GQA; h++) {
        m[h] = -INFINITY; l[h] = 0.f; o[h] = make_float4(0.f, 0.f, 0.f, 0.f);
    }

    int s = s0 + warp;
    if (s < s1) {
        const float* kp = (s == sl) ? knew : (kc + ((size_t)(b * SEQ + s) * NKV + kv) * HD);
        const float* vp = (s == sl) ? vnew : (vc + ((size_t)(b * SEQ + s) * NKV + kv) * HD);
        float4 kk = *(const float4*)(kp + lane * 4);
        float4 vv = *(const float4*)(vp + lane * 4);
        for (;;) {
            int sn = s + 8;
            float4 knx, vnx;
            if (sn < s1) {
                const float* kp2 = (sn == sl) ? knew : (kc + ((size_t)(b * SEQ + sn) * NKV + kv) * HD);
                const float* vp2 = (sn == sl) ? vnew : (vc + ((size_t)(b * SEQ + sn) * NKV + kv) * HD);
                knx = *(const float4*)(kp2 + lane * 4);
                vnx = *(const float4*)(vp2 + lane * 4);
            }
            #pragma unroll
            for (int h = 0; h < GQA; h++) {
                float d = q[h].x * kk.x + q[h].y * kk.y + q[h].z * kk.z + q[h].w * kk.w;
                d += __shfl_xor_sync(0xffffffffu, d, 16);
                d += __shfl_xor_sync(0xffffffffu, d, 8);
                d += __shfl_xor_sync(0xffffffffu, d, 4);
                d += __shfl_xor_sync(0xffffffffu, d, 2);
                d += __shfl_xor_sync(0xffffffffu, d, 1);
                float sc = d * scale;
                float nm = fmaxf(m[h], sc);
                float corr = __expf(m[h] - nm);
                float p = __expf(sc - nm);
                l[h] = l[h] * corr + p;
                o[h].x = o[h].x * corr + p * vv.x;
                o[h].y = o[h].y * corr + p * vv.y;
                o[h].z = o[h].z * corr + p * vv.z;
                o[h].w = o[h].w * corr + p * vv.w;
                m[h] = nm;
            }
            if (sn >= s1) break;
            s = sn; kk = knx; vv = vnx;
        }
    }

    __shared__ float sm[8][GQA], sll[8][GQA];
    __shared__ float so[8][GQA][HD];
    #pragma unroll
    for (int h = 0; h < GQA; h++) {
        if (lane == 0) { sm[warp][h] = m[h]; sll[warp][h] = l[h]; }
        *(float4*)&so[warp][h][lane * 4] = o[h];
    }
    __syncthreads();

    int pbase = ((b * NKV + kv) * NCHUNK + c) * GQA;
    for (int idx = tid; idx < GQA * HD; idx += 256) {
        int h = idx >> 7, d = idx & (HD - 1);
        float M = -INFINITY;
        #pragma unroll
        for (int w = 0; w < 8; w++) M = fmaxf(M, sm[w][h]);
        float acc = 0.f, Ls = 0.f;
        #pragma unroll
        for (int w = 0; w < 8; w++) {
            float cw = __expf(sm[w][h] - M);
            acc += cw * so[w][h][d];
            Ls  += cw * sll[w][h];
        }
        g_po[(pbase + h) * HD + d] = acc;
        if (d == 0) { g_pm[pbase + h] = M; g_pl[pbase + h] = Ls; }
    }
}

// ---------------- combine split-S partials ----------------
__global__ __launch_bounds__(256) void attn_comb_k(
    const int* __restrict__ seq_lens, float* __restrict__ out)
{
    int b  = blockIdx.x >> 2;
    int kv = blockIdx.x & 3;
    int tid = threadIdx.x;
    int sl = seq_lens[b];
    if (sl < 0) sl = 0;
    if (sl > SEQ - 1) sl = SEQ - 1;
    int nch = sl / SCHUNK + 1;
    int base = (b * NKV + kv) * NCHUNK;

    for (int idx = tid; idx < GQA * HD; idx += 256) {
        int h = idx >> 7, d = idx & (HD - 1);
        float M = -INFINITY;
        for (int c = 0; c < nch; c++) M = fmaxf(M, g_pm[(base + c) * GQA + h]);
        float acc = 0.f, Ls = 0.f;
        for (int c = 0; c < nch; c++) {
            float w = __expf(g_pm[(base + c) * GQA + h] - M);
            acc += w * g_po[((base + c) * GQA + h) * HD + d];
            Ls  += w * g_pl[(base + c) * GQA + h];
        }
        out[b * NH * HD + (kv * GQA + h) * HD + d] = acc / Ls;
    }
}

// ---------------- gate: logits, top4, routing tables ----------------
__global__ __launch_bounds__(256) void gate_k(const float* __restrict__ gw)
{
    int b = blockIdx.x, tid = threadIdx.x, warp = tid >> 5, lane = tid & 31;
    __shared__ float lg[NEXP];
    const float* h = g_h2 + b * HDIM;
    for (int e = warp; e < NEXP; e += 8) {
        const float* g = gw + e * HDIM;
        float s = 0.f;
        for (int i = lane; i < HDIM; i += 32) s += h[i] * g[i];
        for (int o = 16; o; o >>= 1) s += __shfl_xor_sync(0xffffffffu, s, o);
        if (lane == 0) lg[e] = s;
    }
    __syncthreads();
    if (tid == 0) {
        float val[TOPK]; int idx[TOPK];
        unsigned used = 0;
        for (int j = 0; j < TOPK; j++) {
            float best = -1e30f; int bi = 0;
            for (int e = 0; e < NEXP; e++)
                if (!((used >> e) & 1u) && lg[e] > best) { best = lg[e]; bi = e; }
            used |= 1u << bi; val[j] = best; idx[j] = bi;
        }
        float s = 0.f, wj[TOPK];
        for (int j = 0; j < TOPK; j++) { wj[j] = expf(val[j] - val[0]); s += wj[j]; }
        float is = 1.f / s;
        for (int j = 0; j < TOPK; j++) {
            int e = idx[j];
            int pos = atomicAdd(&g_cnt[e], 1);
            g_tok [e * BATCH + pos] = b;
            g_slot[e * BATCH + pos] = j;
            g_wt  [e * BATCH + pos] = wj[j] * is;
        }
    }
}

// ---------------- MoE w1: 128 thr, BM=16 BN=64, 2m x 4n x {g,u}, PD4 -----------
// tiles = HDIM/16 = 128 (mult of PD)
__global__ __launch_bounds__(128) void moe_w1_k(const float* __restrict__ w1)
{
    int e = blockIdx.y;
    int cnt = g_cnt[e];
    int m0 = blockIdx.z * 16;
    if (m0 >= cnt) return;
    int ib = blockIdx.x * 64;

    __shared__ float As[PD][16][18];
    __shared__ float Gs[PD][16][68];
    __shared__ float Us[PD][16][68];
    __shared__ int toks[16];

    int tid = threadIdx.x;
    if (tid < 16) toks[tid] = (m0 + tid < cnt) ? g_tok[e * BATCH + m0 + tid]
                                               : g_tok[e * BATCH];
    __syncthreads();

    // A loader: 16m x 16k, 2 scalars/thread (rows am, am+8)
    int am = tid >> 4, ak = tid & 15;           // am 0..7
    const float* Agp0 = g_h2 + (long)toks[am] * HDIM + ak;
    const float* Agp1 = g_h2 + (long)toks[am + 8] * HDIM + ak;
    // W loader: 64 rows x 16k per matrix, 2 float4/thread/matrix
    int ln = tid >> 1, lkq = (tid & 1) * 8;     // ln 0..63
    const float* Ggp = w1 + ((long)e * 2 * IDIM + ib + ln) * HDIM + lkq;
    const float* Ugp = Ggp + (long)IDIM * HDIM;

    int tx = tid & 15, ty = tid >> 4;           // ty 0..7 -> 2m each
    float ag[2][4] = {}, au[2][4] = {};

    float  rA0[PD], rA1[PD];
    float4 rG0[PD], rG1[PD], rU0[PD], rU1[PD];
    const int tiles = HDIM / 16;   // 128
    #pragma unroll
    for (int s = 0; s < PD; s++) {
        rA0[s] = *(Agp0 + s * 16);
        rA1[s] = *(Agp1 + s * 16);
        rG0[s] = *(const float4*)(Ggp + s * 16);
        rG1[s] = *(const float4*)(Ggp + s * 16 + 4);
        rU0[s] = *(const float4*)(Ugp + s * 16);
        rU1[s] = *(const float4*)(Ugp + s * 16 + 4);
    }

    for (int t = 0; t < tiles; t += PD) {
        #pragma unroll
        for (int p = 0; p < PD; p++) {
            As[p][ak][am]     = rA0[p];
            As[p][ak][am + 8] = rA1[p];
            Gs[p][lkq+0][ln] = rG0[p].x; Gs[p][lkq+1][ln] = rG0[p].y;
            Gs[p][lkq+2][ln] = rG0[p].z; Gs[p][lkq+3][ln] = rG0[p].w;
            Gs[p][lkq+4][ln] = rG1[p].x; Gs[p][lkq+5][ln] = rG1[p].y;
            Gs[p][lkq+6][ln] = rG1[p].z; Gs[p][lkq+7][ln] = rG1[p].w;
            Us[p][lkq+0][ln] = rU0[p].x; Us[p][lkq+1][ln] = rU0[p].y;
            Us[p][lkq+2][ln] = rU0[p].z; Us[p][lkq+3][ln] = rU0[p].w;
            Us[p][lkq+4][ln] = rU1[p].x; Us[p][lkq+5][ln] = rU1[p].y;
            Us[p][lkq+6][ln] = rU1[p].z; Us[p][lkq+7][ln] = rU1[p].w;
            if (t + p + PD < tiles) {
                rA0[p] = *(Agp0 + (t + p + PD) * 16);
                rA1[p] = *(Agp1 + (t + p + PD) * 16);
                rG0[p] = *(const float4*)(Ggp + (t + p + PD) * 16);
                rG1[p] = *(const float4*)(Ggp + (t + p + PD) * 16 + 4);
                rU0[p] = *(const float4*)(Ugp + (t + p + PD) * 16);
                rU1[p] = *(const float4*)(Ugp + (t + p + PD) * 16 + 4);
            }
            __syncthreads();
            #pragma unroll
            for (int kk = 0; kk < 16; kk++) {
                float2 a  = *(const float2*)&As[p][kk][ty * 2];
                float4 g4 = *(const float4*)&Gs[p][kk][tx * 4];
                float4 u4 = *(const float4*)&Us[p][kk][tx * 4];
                ag[0][0] = fmaf(a.x, g4.x, ag[0][0]); ag[0][1] = fmaf(a.x, g4.y, ag[0][1]);
                ag[0][2] = fmaf(a.x, g4.z, ag[0][2]); ag[0][3] = fmaf(a.x, g4.w, ag[0][3]);
                ag[1][0] = fmaf(a.y, g4.x, ag[1][0]); ag[1][1] = fmaf(a.y, g4.y, ag[1][1]);
                ag[1][2] = fmaf(a.y, g4.z, ag[1][2]); ag[1][3] = fmaf(a.y, g4.w, ag[1][3]);
                au[0][0] = fmaf(a.x, u4.x, au[0][0]); au[0][1] = fmaf(a.x, u4.y, au[0][1]);
                au[0][2] = fmaf(a.x, u4.z, au[0][2]); au[0][3] = fmaf(a.x, u4.w, au[0][3]);
                au[1][0] = fmaf(a.y, u4.x, au[1][0]); au[1][1] = fmaf(a.y, u4.y, au[1][1]);
                au[1][2] = fmaf(a.y, u4.z, au[1][2]); au[1][3] = fmaf(a.y, u4.w, au[1][3]);
            }
            __syncthreads();
        }
    }

    #pragma unroll
    for (int r = 0; r < 2; r++) {
        int m = m0 + ty * 2 + r;
        if (m < cnt) {
            float4 v;
            float* vp = (float*)&v;
            #pragma unroll
            for (int j = 0; j < 4; j++) {
                float g = ag[r][j];
                vp[j] = g / (1.f + expf(-g)) * au[r][j];
            }
            *(float4*)&g_act[(long)(e * BATCH + m) * IDIM + ib + tx * 4] = v;
        }
    }
}

// ---------------- MoE w2: 128 thr, BM=16 BN=64, 2m x 4n, PD4 -----------
// tiles = IDIM/16 = 48 (mult of PD)
__global__ __launch_bounds__(128) void moe_w2_k(const float* __restrict__ w2)
{
    int e = blockIdx.y;
    int cnt = g_cnt[e];
    int m0 = blockIdx.z * 16;
    if (m0 >= cnt) return;
    int hb = blockIdx.x * 64;

    __shared__ float As[PD][16][18];
    __shared__ float Ws[PD][16][68];

    int tid = threadIdx.x;
    int am = tid >> 4, ak = tid & 15;
    const float* Agp0 = g_act + (long)(e * BATCH + m0 + am) * IDIM + ak;
    const float* Agp1 = g_act + (long)(e * BATCH + m0 + am + 8) * IDIM + ak;
    int ln = tid >> 1, lkq = (tid & 1) * 8;
    const float* Wgp = w2 + ((long)e * HDIM + hb + ln) * IDIM + lkq;

    int tx = tid & 15, ty = tid >> 4;
    float acc[2][4] = {};

    float  rA0[PD], rA1[PD];
    float4 rW0[PD], rW1[PD];
    const int tiles = IDIM / 16;   // 48
    #pragma unroll
    for (int s = 0; s < PD; s++) {
        rA0[s] = *(Agp0 + s * 16);
        rA1[s] = *(Agp1 + s * 16);
        rW0[s] = *(const float4*)(Wgp + s * 16);
        rW1[s] = *(const float4*)(Wgp + s * 16 + 4);
    }

    for (int t = 0; t < tiles; t += PD) {
        #pragma unroll
        for (int p = 0; p < PD; p++) {
            As[p][ak][am]     = rA0[p];
            As[p][ak][am + 8] = rA1[p];
            Ws[p][lkq+0][ln] = rW0[p].x; Ws[p][lkq+1][ln] = rW0[p].y;
            Ws[p][lkq+2][ln] = rW0[p].z; Ws[p][lkq+3][ln] = rW0[p].w;
            Ws[p][lkq+4][ln] = rW1[p].x; Ws[p][lkq+5][ln] = rW1[p].y;
            Ws[p][lkq+6][ln] = rW1[p].z; Ws[p][lkq+7][ln] = rW1[p].w;
            if (t + p + PD < tiles) {
                rA0[p] = *(Agp0 + (t + p + PD) * 16);
                rA1[p] = *(Agp1 + (t + p + PD) * 16);
                rW0[p] = *(const float4*)(Wgp + (t + p + PD) * 16);
                rW1[p] = *(const float4*)(Wgp + (t + p + PD) * 16 + 4);
            }
            __syncthreads();
            #pragma unroll
            for (int kk = 0; kk < 16; kk++) {
                float2 a  = *(const float2*)&As[p][kk][ty * 2];
                float4 w4 = *(const float4*)&Ws[p][kk][tx * 4];
                acc[0][0] = fmaf(a.x, w4.x, acc[0][0]); acc[0][1] = fmaf(a.x, w4.y, acc[0][1]);
                acc[0][2] = fmaf(a.x, w4.z, acc[0][2]); acc[0][3] = fmaf(a.x, w4.w, acc[0][3]);
                acc[1][0] = fmaf(a.y, w4.x, acc[1][0]); acc[1][1] = fmaf(a.y, w4.y, acc[1][1]);
                acc[1][2] = fmaf(a.y, w4.z, acc[1][2]); acc[1][3] = fmaf(a.y, w4.w, acc[1][3]);
            }
            __syncthreads();
        }
    }

    #pragma unroll
    for (int r = 0; r < 2; r++) {
        int m = m0 + ty * 2 + r;
        if (m < cnt) {
            int tok = g_tok [e * BATCH + m];
            int j   = g_slot[e * BATCH + m];
            float w = g_wt  [e * BATCH + m];
            float4 v = make_float4(w * acc[r][0], w * acc[r][1],
                                   w * acc[r][2], w * acc[r][3]);
            *(float4*)&g_ypair[(long)(tok * TOPK + j) * HDIM + hb + tx * 4] = v;
        }
    }
}

// ---------------- finalize: out = hs2 + sum_j ypair ----------------
__global__ __launch_bounds__(256) void finalize_k(float* __restrict__ out)
{
    int idx = blockIdx.x * 256 + threadIdx.x;
    int tok = idx >> 11, hh = idx & (HDIM - 1);
    float s = g_hs2[idx];
    #pragma unroll
    for (int j = 0; j < TOPK; j++) s += g_ypair[(tok * TOPK + j) * HDIM + hh];
    out[idx] = s;
}

// ---------------- launch ----------------
extern "C" void kernel_launch(void* const* d_in, const int* in_sizes, int n_in,
                              void* d_out, int out_size)
{
    static float *p_hn = 0, *p_qkv = 0, *p_attn = 0, *p_hs2 = 0, *p_h2 = 0, *p_part = 0;
    if (!p_hn) {
        cudaGetSymbolAddress((void**)&p_hn,   g_hn);
        cudaGetSymbolAddress((void**)&p_qkv,  g_qkv);
        cudaGetSymbolAddress((void**)&p_attn, g_attn);
        cudaGetSymbolAddress((void**)&p_hs2,  g_hs2);
        cudaGetSymbolAddress((void**)&p_h2,   g_h2);
        cudaGetSymbolAddress((void**)&p_part, g_part);
    }

    const float *hidden = 0, *k_cache = 0, *v_cache = 0, *w_qkv = 0, *b_qkv = 0;
    const float *w_o = 0, *ln1_w = 0, *ln2_w = 0, *gate_w = 0, *w1 = 0, *w2 = 0;
    const int *positions = 0, *seqlens = 0;

    for (int i = 0; i < n_in; i++) {
        long sz = (long)in_sizes[i];
        const void* p = d_in[i];
        if      (sz == (long)BATCH * HDIM)            hidden = (const float*)p;
        else if (sz == (long)BATCH) {
            if (!positions) positions = (const int*)p; else seqlens = (const int*)p;
        }
        else if (sz == (long)BATCH * SEQ * NKV * HD) {
            if (!k_cache) k_cache = (const float*)p; else v_cache = (const float*)p;
        }
        else if (sz == (long)QKV_N * HDIM)            w_qkv  = (const float*)p;
        else if (sz == (long)QKV_N)                   b_qkv  = (const float*)p;
        else if (sz == (long)HDIM * NH * HD)          w_o    = (const float*)p;
        else if (sz == (long)HDIM) {
            if (!ln1_w) ln1_w = (const float*)p; else ln2_w = (const float*)p;
        }
        else if (sz == (long)NEXP * HDIM)             gate_w = (const float*)p;
        else if (sz == (long)NEXP * 2 * IDIM * HDIM)  w1     = (const float*)p;
        else if (sz == (long)NEXP * HDIM * IDIM)      w2     = (const float*)p;
    }
    if (!seqlens && positions) seqlens = positions;
    if (!v_cache) v_cache = k_cache;
    if (!ln2_w)   ln2_w   = ln1_w;

    float* out = (float*)d_out;

    reset_k<<<1, 32>>>();
    rmsnorm_k<<<BATCH, 256>>>(hidden, ln1_w, p_hn);
    // QKV: [64,5120] = hn @ w_qkv^T, K=2048 split 4 (tiles 32), grid 40x4=160
    gemm_part_k<<<dim3(QKV_N / 128, 4), 256>>>(p_hn, w_qkv, p_part, QKV_N, HDIM, 4);
    gemm_reduce_k<<<(64 * QKV_N) / 1024, 256>>>(p_part, b_qkv, nullptr, p_qkv, QKV_N, 4);
    attn_part_k<<<dim3(NCHUNK, NKV, BATCH), 256>>>(k_cache, v_cache, seqlens);
    attn_comb_k<<<BATCH * NKV, 256>>>(seqlens, p_attn);
    // O: [64,2048] = attn @ w_o^T + hidden, K=4096 split 8 (tiles 32), grid 16x8=128
    gemm_part_k<<<dim3(HDIM / 128, 8), 256>>>(p_attn, w_o, p_part, HDIM, NH * HD, 8);
    gemm_reduce_k<<<(64 * HDIM) / 1024, 256>>>(p_part, nullptr, hidden, p_hs2, HDIM, 8);
    rmsnorm_k<<<BATCH, 256>>>(p_hs2, ln2_w, p_h2);
    gate_k<<<BATCH, 256>>>(gate_w);
    moe_w1_k<<<dim3(IDIM / 64, NEXP, 4), 128>>>(w1);
    moe_w2_k<<<dim3(HDIM / 64, NEXP, 4), 128>>>(w2);
    finalize_k<<<(BATCH * HDIM) / 256, 256>>>(out);
}

// round 13
// speedup vs baseline: 1.7837x; 1.6315x over previous
#include <cuda_runtime.h>
#include <cuda_bf16.h>
#include <math.h>

// ---------------- problem constants ----------------
#define BATCH 64
#define HDIM  2048
#define SEQ   2048
#define NH    32
#define NKV   4
#define GQA   8
#define HD    128
#define NEXP  32
#define IDIM  768
#define TOPK  4
#define QKV_N 5120
#define EPS   1e-6f
#define SCHUNK 256
#define NCHUNK (SEQ / SCHUNK)

// ---------------- scratch (device globals) ----------------
// args must come from cudaGetSymbolAddress (ATS host-shadow bug, rounds 1-5).
__device__ float g_hn   [BATCH * HDIM];
__device__ float g_qkv  [BATCH * QKV_N];
__device__ float g_hs2  [BATCH * HDIM];
__device__ float g_h2   [BATCH * HDIM];
__device__ float g_ypair[BATCH * TOPK * HDIM];
__device__ float g_part [4 * BATCH * QKV_N];
__device__ int   g_cnt  [NEXP];
__device__ int   g_tok  [NEXP * BATCH];
__device__ int   g_slot [NEXP * BATCH];
__device__ float g_wt   [NEXP * BATCH];
__device__ float g_pm [BATCH * NKV * NCHUNK * GQA];
__device__ float g_pl [BATCH * NKV * NCHUNK * GQA];
__device__ float g_po [BATCH * NKV * NCHUNK * GQA * HD];
// bf16 split activations
__device__ __nv_bfloat16 g_hnh [BATCH * HDIM];
__device__ __nv_bfloat16 g_hnl [BATCH * HDIM];
__device__ __nv_bfloat16 g_ath [BATCH * NH * HD];
__device__ __nv_bfloat16 g_atl [BATCH * NH * HD];
__device__ __nv_bfloat16 g_h2h [BATCH * HDIM];
__device__ __nv_bfloat16 g_h2l [BATCH * HDIM];
__device__ __nv_bfloat16 g_acth[NEXP * BATCH * IDIM];
__device__ __nv_bfloat16 g_actl[NEXP * BATCH * IDIM];

// ---------------- helpers ----------------
__device__ __forceinline__ void split1(float f, __nv_bfloat16& h, __nv_bfloat16& l) {
    h = __float2bfloat16(f);
    l = __float2bfloat16(f - __bfloat162float(h));
}
__device__ __forceinline__ unsigned pk2(__nv_bfloat16 a, __nv_bfloat16 b) {
    __nv_bfloat162 h; h.x = a; h.y = b;
    return *reinterpret_cast<unsigned*>(&h);
}
__device__ __forceinline__ void mma16816(
    float& c0, float& c1, float& c2, float& c3,
    unsigned a0, unsigned a1, unsigned a2, unsigned a3,
    unsigned b0, unsigned b1)
{
    asm volatile(
        "mma.sync.aligned.m16n8k16.row.col.f32.bf16.bf16.f32 "
        "{%0,%1,%2,%3},{%4,%5,%6,%7},{%8,%9},{%0,%1,%2,%3};"
        : "+f"(c0), "+f"(c1), "+f"(c2), "+f"(c3)
        : "r"(a0), "r"(a1), "r"(a2), "r"(a3), "r"(b0), "r"(b1));
}

// ---------------- reset ----------------
__global__ void reset_k() {
    if (threadIdx.x < NEXP) g_cnt[threadIdx.x] = 0;
}

// ---------------- RMSNorm: fp32 + bf16 split out ----------------
__global__ __launch_bounds__(256) void rmsnorm_k(
    const float* __restrict__ x, const float* __restrict__ w,
    float* __restrict__ y, __nv_bfloat16* __restrict__ yh, __nv_bfloat16* __restrict__ yl)
{
    int b = blockIdx.x, tid = threadIdx.x;
    const float* xb = x + b * HDIM;
    float s = 0.f;
    for (int i = tid; i < HDIM; i += 256) { float v = xb[i]; s += v * v; }
    for (int o = 16; o; o >>= 1) s += __shfl_xor_sync(0xffffffffu, s, o);
    __shared__ float red[8];
    __shared__ float inv;
    if ((tid & 31) == 0) red[tid >> 5] = s;
    __syncthreads();
    if (tid == 0) {
        float t = 0.f;
        #pragma unroll
        for (int i = 0; i < 8; i++) t += red[i];
        inv = rsqrtf(t * (1.f / HDIM) + EPS);
    }
    __syncthreads();
    float iv = inv;
    for (int i = tid; i < HDIM; i += 256) {
        float v = xb[i] * iv * w[i];
        y[b * HDIM + i] = v;
        __nv_bfloat16 h, l; split1(v, h, l);
        yh[b * HDIM + i] = h; yl[b * HDIM + i] = l;
    }
}

// ---------------- tensor GEMM partial: part[ks][64][N] = A@W^T (bf16x3) --------
// BM=64 BN=64 BK=32, 256 thr, PD=2 static. tiles = K/ksplit/32 must be even.
__global__ __launch_bounds__(256) void gemm_part_tc(
    const __nv_bfloat16* __restrict__ Ah, const __nv_bfloat16* __restrict__ Al,
    const float* __restrict__ W, float* __restrict__ part, int N, int K, int ksplit)
{
    __shared__ __nv_bfloat16 sAh[2][64][40], sAl[2][64][40];
    __shared__ __nv_bfloat16 sWh[2][64][40], sWl[2][64][40];
    int nb = blockIdx.x * 64;
    int ks = blockIdx.y;
    int klen = K / ksplit, kbeg = ks * klen, tiles = klen / 32;
    int tid = threadIdx.x, lane = tid & 31, warp = tid >> 5;
    int mw = warp & 3, nw = warp >> 2;
    int gr = lane >> 2, tc = lane & 3;

    int lm = tid >> 2, lk8 = (tid & 3) * 8;
    const __nv_bfloat16* Agh = Ah + (long)lm * K + kbeg + lk8;
    const __nv_bfloat16* Agl = Al + (long)lm * K + kbeg + lk8;
    const float* Wg = W + (long)(nb + lm) * K + kbeg + lk8;

    float acc[4][4] = {};
    uint4 rah[2], ral[2];
    float4 rw[2][2];
    #pragma unroll
    for (int s = 0; s < 2; s++) {
        rah[s] = *(const uint4*)(Agh + s * 32);
        ral[s] = *(const uint4*)(Agl + s * 32);
        rw[s][0] = *(const float4*)(Wg + s * 32);
        rw[s][1] = *(const float4*)(Wg + s * 32 + 4);
    }

    for (int t = 0; t < tiles; t += 2) {
        #pragma unroll
        for (int p = 0; p < 2; p++) {
            *(uint4*)&sAh[p][lm][lk8] = rah[p];
            *(uint4*)&sAl[p][lm][lk8] = ral[p];
            {
                float f[8] = {rw[p][0].x, rw[p][0].y, rw[p][0].z, rw[p][0].w,
                              rw[p][1].x, rw[p][1].y, rw[p][1].z, rw[p][1].w};
                __nv_bfloat16 h[8], l[8];
                #pragma unroll
                for (int i = 0; i < 8; i++) split1(f[i], h[i], l[i]);
                uint4 uh = make_uint4(pk2(h[0],h[1]), pk2(h[2],h[3]), pk2(h[4],h[5]), pk2(h[6],h[7]));
                uint4 ul = make_uint4(pk2(l[0],l[1]), pk2(l[2],l[3]), pk2(l[4],l[5]), pk2(l[6],l[7]));
                *(uint4*)&sWh[p][lm][lk8] = uh;
                *(uint4*)&sWl[p][lm][lk8] = ul;
            }
            if (t + p + 2 < tiles) {
                rah[p] = *(const uint4*)(Agh + (t + p + 2) * 32);
                ral[p] = *(const uint4*)(Agl + (t + p + 2) * 32);
                rw[p][0] = *(const float4*)(Wg + (t + p + 2) * 32);
                rw[p][1] = *(const float4*)(Wg + (t + p + 2) * 32 + 4);
            }
            __syncthreads();
            #pragma unroll
            for (int k16 = 0; k16 < 2; k16++) {
                int kc = k16 * 16 + tc * 2;
                int ra = mw * 16 + gr;
                unsigned ah0 = *(const unsigned*)&sAh[p][ra][kc];
                unsigned ah1 = *(const unsigned*)&sAh[p][ra + 8][kc];
                unsigned ah2 = *(const unsigned*)&sAh[p][ra][kc + 8];
                unsigned ah3 = *(const unsigned*)&sAh[p][ra + 8][kc + 8];
                unsigned al0 = *(const unsigned*)&sAl[p][ra][kc];
                unsigned al1 = *(const unsigned*)&sAl[p][ra + 8][kc];
                unsigned al2 = *(const unsigned*)&sAl[p][ra][kc + 8];
                unsigned al3 = *(const unsigned*)&sAl[p][ra + 8][kc + 8];
                #pragma unroll
                for (int j = 0; j < 4; j++) {
                    int n = nw * 32 + j * 8 + gr;
                    unsigned bh0 = *(const unsigned*)&sWh[p][n][kc];
                    unsigned bh1 = *(const unsigned*)&sWh[p][n][kc + 8];
                    unsigned bl0 = *(const unsigned*)&sWl[p][n][kc];
                    unsigned bl1 = *(const unsigned*)&sWl[p][n][kc + 8];
                    mma16816(acc[j][0], acc[j][1], acc[j][2], acc[j][3],
                             ah0, ah1, ah2, ah3, bh0, bh1);
                    mma16816(acc[j][0], acc[j][1], acc[j][2], acc[j][3],
                             ah0, ah1, ah2, ah3, bl0, bl1);
                    mma16816(acc[j][0], acc[j][1], acc[j][2], acc[j][3],
                             al0, al1, al2, al3, bh0, bh1);
                }
            }
            __syncthreads();
        }
    }

    #pragma unroll
    for (int j = 0; j < 4; j++) {
        int col = nb + nw * 32 + j * 8 + tc * 2;
        long r0 = (long)(ks * 64 + mw * 16 + gr) * N + col;
        *(float2*)&part[r0] = make_float2(acc[j][0], acc[j][1]);
        *(float2*)&part[r0 + 8L * N] = make_float2(acc[j][2], acc[j][3]);
    }
}

// ---------------- GEMM reduce ----------------
__global__ __launch_bounds__(256) void gemm_reduce_k(
    const float* __restrict__ part, const float* __restrict__ bias,
    const float* __restrict__ res, float* __restrict__ C, int N, int ksplit)
{
    int idx = (blockIdx.x * 256 + threadIdx.x) * 4;
    int m = idx / N, n = idx % N;
    float4 s = bias ? *(const float4*)&bias[n] : make_float4(0.f, 0.f, 0.f, 0.f);
    for (int ks = 0; ks < ksplit; ks++) {
        float4 p = *(const float4*)&part[((long)(ks * 64 + m)) * N + n];
        s.x += p.x; s.y += p.y; s.z += p.z; s.w += p.w;
    }
    if (res) {
        float4 r = *(const float4*)&res[idx];
        s.x += r.x; s.y += r.y; s.z += r.z; s.w += r.w;
    }
    *(float4*)&C[idx] = s;
}

// ---------------- split-S GQA flash-decode ----------------
__global__ __launch_bounds__(256) void attn_part_k(
    const float* __restrict__ kc, const float* __restrict__ vc,
    const int* __restrict__ seq_lens)
{
    int c  = blockIdx.x;
    int kv = blockIdx.y;
    int b  = blockIdx.z;
    int tid = threadIdx.x, warp = tid >> 5, lane = tid & 31;
    int sl = seq_lens[b];
    if (sl < 0) sl = 0;
    if (sl > SEQ - 1) sl = SEQ - 1;
    int L  = sl + 1;
    int s0 = c * SCHUNK;
    if (s0 >= L) return;
    int s1 = s0 + SCHUNK; if (s1 > L) s1 = L;
    const float scale = 0.08838834764831845f;

    const float* qbase = g_qkv + b * QKV_N + kv * GQA * HD;
    const float* knew  = g_qkv + b * QKV_N + NH * HD + kv * HD;
    const float* vnew  = g_qkv + b * QKV_N + (NH + NKV) * HD + kv * HD;

    float4 q[GQA];
    #pragma unroll
    for (int h = 0; h < GQA; h++) q[h] = *(const float4*)(qbase + h * HD + lane * 4);

    float m[GQA], l[GQA];
    float4 o[GQA];
    #pragma unroll
    for (int h = 0; h < GQA; h++) {
        m[h] = -INFINITY; l[h] = 0.f; o[h] = make_float4(0.f, 0.f, 0.f, 0.f);
    }

    int s = s0 + warp;
    if (s < s1) {
        const float* kp = (s == sl) ? knew : (kc + ((size_t)(b * SEQ + s) * NKV + kv) * HD);
        const float* vp = (s == sl) ? vnew : (vc + ((size_t)(b * SEQ + s) * NKV + kv) * HD);
        float4 kk = *(const float4*)(kp + lane * 4);
        float4 vv = *(const float4*)(vp + lane * 4);
        for (;;) {
            int sn = s + 8;
            float4 knx, vnx;
            if (sn < s1) {
                const float* kp2 = (sn == sl) ? knew : (kc + ((size_t)(b * SEQ + sn) * NKV + kv) * HD);
                const float* vp2 = (sn == sl) ? vnew : (vc + ((size_t)(b * SEQ + sn) * NKV + kv) * HD);
                knx = *(const float4*)(kp2 + lane * 4);
                vnx = *(const float4*)(vp2 + lane * 4);
            }
            #pragma unroll
            for (int h = 0; h < GQA; h++) {
                float d = q[h].x * kk.x + q[h].y * kk.y + q[h].z * kk.z + q[h].w * kk.w;
                d += __shfl_xor_sync(0xffffffffu, d, 16);
                d += __shfl_xor_sync(0xffffffffu, d, 8);
                d += __shfl_xor_sync(0xffffffffu, d, 4);
                d += __shfl_xor_sync(0xffffffffu, d, 2);
                d += __shfl_xor_sync(0xffffffffu, d, 1);
                float sc = d * scale;
                float nm = fmaxf(m[h], sc);
                float corr = __expf(m[h] - nm);
                float p = __expf(sc - nm);
                l[h] = l[h] * corr + p;
                o[h].x = o[h].x * corr + p * vv.x;
                o[h].y = o[h].y * corr + p * vv.y;
                o[h].z = o[h].z * corr + p * vv.z;
                o[h].w = o[h].w * corr + p * vv.w;
                m[h] = nm;
            }
            if (sn >= s1) break;
            s = sn; kk = knx; vv = vnx;
        }
    }

    __shared__ float sm[8][GQA], sll[8][GQA];
    __shared__ float so[8][GQA][HD];
    #pragma unroll
    for (int h = 0; h < GQA; h++) {
        if (lane == 0) { sm[warp][h] = m[h]; sll[warp][h] = l[h]; }
        *(float4*)&so[warp][h][lane * 4] = o[h];
    }
    __syncthreads();

    int pbase = ((b * NKV + kv) * NCHUNK + c) * GQA;
    for (int idx = tid; idx < GQA * HD; idx += 256) {
        int h = idx >> 7, d = idx & (HD - 1);
        float M = -INFINITY;
        #pragma unroll
        for (int w = 0; w < 8; w++) M = fmaxf(M, sm[w][h]);
        float acc = 0.f, Ls = 0.f;
        #pragma unroll
        for (int w = 0; w < 8; w++) {
            float cw = __expf(sm[w][h] - M);
            acc += cw * so[w][h][d];
            Ls  += cw * sll[w][h];
        }
        g_po[(pbase + h) * HD + d] = acc;
        if (d == 0) { g_pm[pbase + h] = M; g_pl[pbase + h] = Ls; }
    }
}

// ---------------- combine split-S partials -> bf16 split ----------------
__global__ __launch_bounds__(256) void attn_comb_k(
    const int* __restrict__ seq_lens,
    __nv_bfloat16* __restrict__ outh, __nv_bfloat16* __restrict__ outl)
{
    int b  = blockIdx.x >> 2;
    int kv = blockIdx.x & 3;
    int tid = threadIdx.x;
    int sl = seq_lens[b];
    if (sl < 0) sl = 0;
    if (sl > SEQ - 1) sl = SEQ - 1;
    int nch = sl / SCHUNK + 1;
    int base = (b * NKV + kv) * NCHUNK;

    for (int idx = tid; idx < GQA * HD; idx += 256) {
        int h = idx >> 7, d = idx & (HD - 1);
        float M = -INFINITY;
        for (int c = 0; c < nch; c++) M = fmaxf(M, g_pm[(base + c) * GQA + h]);
        float acc = 0.f, Ls = 0.f;
        for (int c = 0; c < nch; c++) {
            float w = __expf(g_pm[(base + c) * GQA + h] - M);
            acc += w * g_po[((base + c) * GQA + h) * HD + d];
            Ls  += w * g_pl[(base + c) * GQA + h];
        }
        float v = acc / Ls;
        __nv_bfloat16 hh, ll; split1(v, hh, ll);
        long o = (long)b * NH * HD + (kv * GQA + h) * HD + d;
        outh[o] = hh; outl[o] = ll;
    }
}

// ---------------- gate ----------------
__global__ __launch_bounds__(256) void gate_k(const float* __restrict__ gw)
{
    int b = blockIdx.x, tid = threadIdx.x, warp = tid >> 5, lane = tid & 31;
    __shared__ float lg[NEXP];
    const float* h = g_h2 + b * HDIM;
    for (int e = warp; e < NEXP; e += 8) {
        const float* g = gw + e * HDIM;
        float s = 0.f;
        for (int i = lane; i < HDIM; i += 32) s += h[i] * g[i];
        for (int o = 16; o; o >>= 1) s += __shfl_xor_sync(0xffffffffu, s, o);
        if (lane == 0) lg[e] = s;
    }
    __syncthreads();
    if (tid == 0) {
        float val[TOPK]; int idx[TOPK];
        unsigned used = 0;
        for (int j = 0; j < TOPK; j++) {
            float best = -1e30f; int bi = 0;
            for (int e = 0; e < NEXP; e++)
                if (!((used >> e) & 1u) && lg[e] > best) { best = lg[e]; bi = e; }
            used |= 1u << bi; val[j] = best; idx[j] = bi;
        }
        float s = 0.f, wj[TOPK];
        for (int j = 0; j < TOPK; j++) { wj[j] = expf(val[j] - val[0]); s += wj[j]; }
        float is = 1.f / s;
        for (int j = 0; j < TOPK; j++) {
            int e = idx[j];
            int pos = atomicAdd(&g_cnt[e], 1);
            g_tok [e * BATCH + pos] = b;
            g_slot[e * BATCH + pos] = j;
            g_wt  [e * BATCH + pos] = wj[j] * is;
        }
    }
}

// ---------------- MoE w1 (tensor, bf16x3, fused SwiGLU) ----------------
// grid (IDIM/64, NEXP, 4), 256 thr. Computes [16, 64 G-cols + 64 U-cols].
__global__ __launch_bounds__(256) void moe_w1_tc(const float* __restrict__ w1)
{
    int e = blockIdx.y;
    int cnt = g_cnt[e];
    int m0 = blockIdx.z * 16;
    if (m0 >= cnt) return;
    int ib = blockIdx.x * 64;

    __shared__ __align__(16) char SM[46080];
    __nv_bfloat16* pAh = (__nv_bfloat16*)SM;        // [2][16][40]  1280 el
    __nv_bfloat16* pAl = pAh + 1280;                // [2][16][40]
    __nv_bfloat16* pWh = pAl + 1280;                // [2][128][40] 10240 el
    __nv_bfloat16* pWl = pWh + 10240;               // [2][128][40]
    float* Csm = (float*)SM;                        // [16][132] overlay (after loop)
    __shared__ int toks[16];

    int tid = threadIdx.x, lane = tid & 31, warp = tid >> 5;
    int gr = lane >> 2, tc = lane & 3;
    if (tid < 16) toks[tid] = (m0 + tid < cnt) ? g_tok[e * BATCH + m0 + tid]
                                               : g_tok[e * BATCH];
    __syncthreads();

    // A loader: 16 rows x 32k bf16, 1 uint/thread/matrix
    int ar = tid >> 4, akp = (tid & 15) * 2;
    const __nv_bfloat16* Agh = g_h2h + (long)toks[ar] * HDIM + akp;
    const __nv_bfloat16* Agl = g_h2l + (long)toks[ar] * HDIM + akp;
    // W loader: 128 rows x 32k fp32, 4 float4/thread
    int lw = tid >> 1, wk = (tid & 1) * 16;
    long wrow = (long)e * 2 * IDIM + ((lw < 64) ? (ib + lw) : (IDIM + ib + lw - 64));
    const float* Wg = w1 + wrow * HDIM + wk;

    const int tiles = HDIM / 32;   // 64
    float acc[2][4] = {};

    unsigned rah[2], ral[2];
    float4 rw[2][4];
    #pragma unroll
    for (int s = 0; s < 2; s++) {
        rah[s] = *(const unsigned*)(Agh + s * 32);
        ral[s] = *(const unsigned*)(Agl + s * 32);
        #pragma unroll
        for (int q = 0; q < 4; q++) rw[s][q] = *(const float4*)(Wg + s * 32 + q * 4);
    }

    for (int t = 0; t < tiles; t += 2) {
        #pragma unroll
        for (int p = 0; p < 2; p++) {
            *(unsigned*)&pAh[p * 640 + ar * 40 + akp] = rah[p];
            *(unsigned*)&pAl[p * 640 + ar * 40 + akp] = ral[p];
            {
                float f[16];
                #pragma unroll
                for (int q = 0; q < 4; q++) {
                    f[q*4+0] = rw[p][q].x; f[q*4+1] = rw[p][q].y;
                    f[q*4+2] = rw[p][q].z; f[q*4+3] = rw[p][q].w;
                }
                __nv_bfloat16 h[16], l[16];
                #pragma unroll
                for (int i = 0; i < 16; i++) split1(f[i], h[i], l[i]);
                uint4 uh0 = make_uint4(pk2(h[0],h[1]), pk2(h[2],h[3]), pk2(h[4],h[5]), pk2(h[6],h[7]));
                uint4 uh1 = make_uint4(pk2(h[8],h[9]), pk2(h[10],h[11]), pk2(h[12],h[13]), pk2(h[14],h[15]));
                uint4 ul0 = make_uint4(pk2(l[0],l[1]), pk2(l[2],l[3]), pk2(l[4],l[5]), pk2(l[6],l[7]));
                uint4 ul1 = make_uint4(pk2(l[8],l[9]), pk2(l[10],l[11]), pk2(l[12],l[13]), pk2(l[14],l[15]));
                long o = p * 5120 + lw * 40 + wk;
                *(uint4*)&pWh[o] = uh0; *(uint4*)&pWh[o + 8] = uh1;
                *(uint4*)&pWl[o] = ul0; *(uint4*)&pWl[o + 8] = ul1;
            }
            if (t + p + 2 < tiles) {
                rah[p] = *(const unsigned*)(Agh + (t + p + 2) * 32);
                ral[p] = *(const unsigned*)(Agl + (t + p + 2) * 32);
                #pragma unroll
                for (int q = 0; q < 4; q++)
                    rw[p][q] = *(const float4*)(Wg + (t + p + 2) * 32 + q * 4);
            }
            __syncthreads();
            #pragma unroll
            for (int k16 = 0; k16 < 2; k16++) {
                int kc = k16 * 16 + tc * 2;
                unsigned ah0 = *(const unsigned*)&pAh[p * 640 + gr * 40 + kc];
                unsigned ah1 = *(const unsigned*)&pAh[p * 640 + (gr + 8) * 40 + kc];
                unsigned ah2 = *(const unsigned*)&pAh[p * 640 + gr * 40 + kc + 8];
                unsigned ah3 = *(const unsigned*)&pAh[p * 640 + (gr + 8) * 40 + kc + 8];
                unsigned al0 = *(const unsigned*)&pAl[p * 640 + gr * 40 + kc];
                unsigned al1 = *(const unsigned*)&pAl[p * 640 + (gr + 8) * 40 + kc];
                unsigned al2 = *(const unsigned*)&pAl[p * 640 + gr * 40 + kc + 8];
                unsigned al3 = *(const unsigned*)&pAl[p * 640 + (gr + 8) * 40 + kc + 8];
                #pragma unroll
                for (int j = 0; j < 2; j++) {
                    int n = warp * 16 + j * 8 + gr;
                    unsigned bh0 = *(const unsigned*)&pWh[p * 5120 + n * 40 + kc];
                    unsigned bh1 = *(const unsigned*)&pWh[p * 5120 + n * 40 + kc + 8];
                    unsigned bl0 = *(const unsigned*)&pWl[p * 5120 + n * 40 + kc];
                    unsigned bl1 = *(const unsigned*)&pWl[p * 5120 + n * 40 + kc + 8];
                    mma16816(acc[j][0], acc[j][1], acc[j][2], acc[j][3],
                             ah0, ah1, ah2, ah3, bh0, bh1);
                    mma16816(acc[j][0], acc[j][1], acc[j][2], acc[j][3],
                             ah0, ah1, ah2, ah3, bl0, bl1);
                    mma16816(acc[j][0], acc[j][1], acc[j][2], acc[j][3],
                             al0, al1, al2, al3, bh0, bh1);
                }
            }
            __syncthreads();
        }
    }

    // write fragments to Csm (overlays pipeline smem; all reads done)
    #pragma unroll
    for (int j = 0; j < 2; j++) {
        int col = warp * 16 + j * 8 + tc * 2;
        Csm[gr * 132 + col] = acc[j][0];
        Csm[gr * 132 + col + 1] = acc[j][1];
        Csm[(gr + 8) * 132 + col] = acc[j][2];
        Csm[(gr + 8) * 132 + col + 1] = acc[j][3];
    }
    __syncthreads();

    // SwiGLU epilogue: act = silu(G) * U, split to bf16
    #pragma unroll
    for (int it = 0; it < 4; it++) {
        int idx = tid + it * 256;
        int m = idx >> 6, n = idx & 63;
        if (m0 + m < cnt) {
            float gg = Csm[m * 132 + n];
            float uu = Csm[m * 132 + 64 + n];
            float a = gg / (1.f + expf(-gg)) * uu;
            __nv_bfloat16 h, l; split1(a, h, l);
            long o = (long)(e * BATCH + m0 + m) * IDIM + ib + n;
            g_acth[o] = h; g_actl[o] = l;
        }
    }
}

// ---------------- MoE w2 (tensor, bf16x3, weighted scatter) ----------------
// grid (HDIM/64, NEXP, 4), 128 thr.
__global__ __launch_bounds__(128) void moe_w2_tc(const float* __restrict__ w2)
{
    int e = blockIdx.y;
    int cnt = g_cnt[e];
    int m0 = blockIdx.z * 16;
    if (m0 >= cnt) return;
    int hb = blockIdx.x * 64;

    __shared__ __nv_bfloat16 sAh[2][16][40], sAl[2][16][40];
    __shared__ __nv_bfloat16 sWh[2][64][40], sWl[2][64][40];

    int tid = threadIdx.x, lane = tid & 31, warp = tid >> 5;
    int gr = lane >> 2, tc = lane & 3;

    // A loader: 16 rows x 32k, uint2/thread/matrix
    int ar = tid >> 3, akp = (tid & 7) * 4;
    const __nv_bfloat16* Agh = g_acth + (long)(e * BATCH + m0 + ar) * IDIM + akp;
    const __nv_bfloat16* Agl = g_actl + (long)(e * BATCH + m0 + ar) * IDIM + akp;
    // W loader: 64 rows x 32k fp32, 4 float4/thread
    int lw = tid >> 1, wk = (tid & 1) * 16;
    const float* Wg = w2 + ((long)e * HDIM + hb + lw) * IDIM + wk;

    const int tiles = IDIM / 32;   // 24
    float acc[2][4] = {};

    uint2 rah[2], ral[2];
    float4 rw[2][4];
    #pragma unroll
    for (int s = 0; s < 2; s++) {
        rah[s] = *(const uint2*)(Agh + s * 32);
        ral[s] = *(const uint2*)(Agl + s * 32);
        #pragma unroll
        for (int q = 0; q < 4; q++) rw[s][q] = *(const float4*)(Wg + s * 32 + q * 4);
    }

    for (int t = 0; t < tiles; t += 2) {
        #pragma unroll
        for (int p = 0; p < 2; p++) {
            *(uint2*)&sAh[p][ar][akp] = rah[p];
            *(uint2*)&sAl[p][ar][akp] = ral[p];
            {
                float f[16];
                #pragma unroll
                for (int q = 0; q < 4; q++) {
                    f[q*4+0] = rw[p][q].x; f[q*4+1] = rw[p][q].y;
                    f[q*4+2] = rw[p][q].z; f[q*4+3] = rw[p][q].w;
                }
                __nv_bfloat16 h[16], l[16];
                #pragma unroll
                for (int i = 0; i < 16; i++) split1(f[i], h[i], l[i]);
                uint4 uh0 = make_uint4(pk2(h[0],h[1]), pk2(h[2],h[3]), pk2(h[4],h[5]), pk2(h[6],h[7]));
                uint4 uh1 = make_uint4(pk2(h[8],h[9]), pk2(h[10],h[11]), pk2(h[12],h[13]), pk2(h[14],h[15]));
                uint4 ul0 = make_uint4(pk2(l[0],l[1]), pk2(l[2],l[3]), pk2(l[4],l[5]), pk2(l[6],l[7]));
                uint4 ul1 = make_uint4(pk2(l[8],l[9]), pk2(l[10],l[11]), pk2(l[12],l[13]), pk2(l[14],l[15]));
                *(uint4*)&sWh[p][lw][wk] = uh0; *(uint4*)&sWh[p][lw][wk + 8] = uh1;
                *(uint4*)&sWl[p][lw][wk] = ul0; *(uint4*)&sWl[p][lw][wk + 8] = ul1;
            }
            if (t + p + 2 < tiles) {
                rah[p] = *(const uint2*)(Agh + (t + p + 2) * 32);
                ral[p] = *(const uint2*)(Agl + (t + p + 2) * 32);
                #pragma unroll
                for (int q = 0; q < 4; q++)
                    rw[p][q] = *(const float4*)(Wg + (t + p + 2) * 32 + q * 4);
            }
            __syncthreads();
            #pragma unroll
            for (int k16 = 0; k16 < 2; k16++) {
                int kc = k16 * 16 + tc * 2;
                unsigned ah0 = *(const unsigned*)&sAh[p][gr][kc];
                unsigned ah1 = *(const unsigned*)&sAh[p][gr + 8][kc];
                unsigned ah2 = *(const unsigned*)&sAh[p][gr][kc + 8];
                unsigned ah3 = *(const unsigned*)&sAh[p][gr + 8][kc + 8];
                unsigned al0 = *(const unsigned*)&sAl[p][gr][kc];
                unsigned al1 = *(const unsigned*)&sAl[p][gr + 8][kc];
                unsigned al2 = *(const unsigned*)&sAl[p][gr][kc + 8];
                unsigned al3 = *(const unsigned*)&sAl[p][gr + 8][kc + 8];
                #pragma unroll
                for (int j = 0; j < 2; j++) {
                    int n = warp * 16 + j * 8 + gr;
                    unsigned bh0 = *(const unsigned*)&sWh[p][n][kc];
                    unsigned bh1 = *(const unsigned*)&sWh[p][n][kc + 8];
                    unsigned bl0 = *(const unsigned*)&sWl[p][n][kc];
                    unsigned bl1 = *(const unsigned*)&sWl[p][n][kc + 8];
                    mma16816(acc[j][0], acc[j][1], acc[j][2], acc[j][3],
                             ah0, ah1, ah2, ah3, bh0, bh1);
                    mma16816(acc[j][0], acc[j][1], acc[j][2], acc[j][3],
                             ah0, ah1, ah2, ah3, bl0, bl1);
                    mma16816(acc[j][0], acc[j][1], acc[j][2], acc[j][3],
                             al0, al1, al2, al3, bh0, bh1);
                }
            }
            __syncthreads();
        }
    }

    // scatter: rows gr, gr+8 (mask by cnt)
    #pragma unroll
    for (int j = 0; j < 2; j++) {
        int col = hb + warp * 16 + j * 8 + tc * 2;
        int m1 = m0 + gr, m2 = m0 + gr + 8;
        if (m1 < cnt) {
            int tok = g_tok[e * BATCH + m1], sj = g_slot[e * BATCH + m1];
            float w = g_wt[e * BATCH + m1];
            float* yp = &g_ypair[(long)(tok * TOPK + sj) * HDIM + col];
            yp[0] = w * acc[j][0]; yp[1] = w * acc[j][1];
        }
        if (m2 < cnt) {
            int tok = g_tok[e * BATCH + m2], sj = g_slot[e * BATCH + m2];
            float w = g_wt[e * BATCH + m2];
            float* yp = &g_ypair[(long)(tok * TOPK + sj) * HDIM + col];
            yp[0] = w * acc[j][2]; yp[1] = w * acc[j][3];
        }
    }
}

// ---------------- finalize ----------------
__global__ __launch_bounds__(256) void finalize_k(float* __restrict__ out)
{
    int idx = blockIdx.x * 256 + threadIdx.x;
    int tok = idx >> 11, hh = idx & (HDIM - 1);
    float s = g_hs2[idx];
    #pragma unroll
    for (int j = 0; j < TOPK; j++) s += g_ypair[(tok * TOPK + j) * HDIM + hh];
    out[idx] = s;
}

// ---------------- launch ----------------
extern "C" void kernel_launch(void* const* d_in, const int* in_sizes, int n_in,
                              void* d_out, int out_size)
{
    static float *p_hn = 0, *p_qkv = 0, *p_hs2 = 0, *p_h2 = 0, *p_part = 0;
    static __nv_bfloat16 *p_hnh = 0, *p_hnl = 0, *p_ath = 0, *p_atl = 0, *p_h2h = 0, *p_h2l = 0;
    if (!p_hn) {
        cudaGetSymbolAddress((void**)&p_hn,   g_hn);
        cudaGetSymbolAddress((void**)&p_qkv,  g_qkv);
        cudaGetSymbolAddress((void**)&p_hs2,  g_hs2);
        cudaGetSymbolAddress((void**)&p_h2,   g_h2);
        cudaGetSymbolAddress((void**)&p_part, g_part);
        cudaGetSymbolAddress((void**)&p_hnh,  g_hnh);
        cudaGetSymbolAddress((void**)&p_hnl,  g_hnl);
        cudaGetSymbolAddress((void**)&p_ath,  g_ath);
        cudaGetSymbolAddress((void**)&p_atl,  g_atl);
        cudaGetSymbolAddress((void**)&p_h2h,  g_h2h);
        cudaGetSymbolAddress((void**)&p_h2l,  g_h2l);
    }

    const float *hidden = 0, *k_cache = 0, *v_cache = 0, *w_qkv = 0, *b_qkv = 0;
    const float *w_o = 0, *ln1_w = 0, *ln2_w = 0, *gate_w = 0, *w1 = 0, *w2 = 0;
    const int *positions = 0, *seqlens = 0;

    for (int i = 0; i < n_in; i++) {
        long sz = (long)in_sizes[i];
        const void* p = d_in[i];
        if      (sz == (long)BATCH * HDIM)            hidden = (const float*)p;
        else if (sz == (long)BATCH) {
            if (!positions) positions = (const int*)p; else seqlens = (const int*)p;
        }
        else if (sz == (long)BATCH * SEQ * NKV * HD) {
            if (!k_cache) k_cache = (const float*)p; else v_cache = (const float*)p;
        }
        else if (sz == (long)QKV_N * HDIM)            w_qkv  = (const float*)p;
        else if (sz == (long)QKV_N)                   b_qkv  = (const float*)p;
        else if (sz == (long)HDIM * NH * HD)          w_o    = (const float*)p;
        else if (sz == (long)HDIM) {
            if (!ln1_w) ln1_w = (const float*)p; else ln2_w = (const float*)p;
        }
        else if (sz == (long)NEXP * HDIM)             gate_w = (const float*)p;
        else if (sz == (long)NEXP * 2 * IDIM * HDIM)  w1     = (const float*)p;
        else if (sz == (long)NEXP * HDIM * IDIM)      w2     = (const float*)p;
    }
    if (!seqlens && positions) seqlens = positions;
    if (!v_cache) v_cache = k_cache;
    if (!ln2_w)   ln2_w   = ln1_w;

    float* out = (float*)d_out;

    reset_k<<<1, 32>>>();
    rmsnorm_k<<<BATCH, 256>>>(hidden, ln1_w, p_hn, p_hnh, p_hnl);
    // QKV: K=2048 ksplit 4 (tiles 16)
    gemm_part_tc<<<dim3(QKV_N / 64, 4), 256>>>(p_hnh, p_hnl, w_qkv, p_part, QKV_N, HDIM, 4);
    gemm_reduce_k<<<(64 * QKV_N) / 1024, 256>>>(p_part, b_qkv, nullptr, p_qkv, QKV_N, 4);
    attn_part_k<<<dim3(NCHUNK, NKV, BATCH), 256>>>(k_cache, v_cache, seqlens);
    attn_comb_k<<<BATCH * NKV, 256>>>(seqlens, p_ath, p_atl);
    // O: K=4096 ksplit 8 (tiles 16)
    gemm_part_tc<<<dim3(HDIM / 64, 8), 256>>>(p_ath, p_atl, w_o, p_part, HDIM, NH * HD, 8);
    gemm_reduce_k<<<(64 * HDIM) / 1024, 256>>>(p_part, nullptr, hidden, p_hs2, HDIM, 8);
    rmsnorm_k<<<BATCH, 256>>>(p_hs2, ln2_w, p_h2, p_h2h, p_h2l);
    gate_k<<<BATCH, 256>>>(gate_w);
    moe_w1_tc<<<dim3(IDIM / 64, NEXP, 4), 256>>>(w1);
    moe_w2_tc<<<dim3(HDIM / 64, NEXP, 4), 128>>>(w2);
    finalize_k<<<(BATCH * HDIM) / 256, 256>>>(out);
}